// round 15
// baseline (speedup 1.0000x reference)
#include <cuda_runtime.h>

// LSTM_40948218200110: B=4096, T=1024, I=8, H=4 (PyTorch gate order) + FC[H->1].
// R13: 4 lanes per element (lane k = hidden unit; each lane owns ALL 4 gate rows
// of its unit -> no activation-gather round; i,f,g,o local). ONE dependent
// shuffle round per step: 3 parallel h-butterflies (masks 1,2,3), recurrent
// weights k^m-permuted. Packed fma.rn.f32x2 for all dot products. x staged in
// smem (conflict-free stride-9 layout, broadcast LDS.128), block-wide sync
// double buffering (the variant R11/R12 showed is fastest).
// 512 warps, BLOCK=64, EPB=16, grid=256.

#define T_STEPS 1024
#define I_DIM   8
#define EPB     16            // elements per block (2 warps x 8)
#define BLOCK   64
#define CH_STEPS 8            // timesteps per smem chunk
#define NCHUNK  (T_STEPS / CH_STEPS)   // 128

typedef unsigned long long ull;

__device__ __forceinline__ float tanh_fast(float x) {
    float y;
    asm("tanh.approx.f32 %0, %1;" : "=f"(y) : "f"(x));
    return y;
}
__device__ __forceinline__ ull ffma2(ull a, ull b, ull c) {
    ull d;
    asm("fma.rn.f32x2 %0, %1, %2, %3;" : "=l"(d) : "l"(a), "l"(b), "l"(c));
    return d;
}
__device__ __forceinline__ ull pack2(float lo, float hi) {
    ull d;
    asm("mov.b64 %0, {%1, %2};" : "=l"(d) : "f"(lo), "f"(hi));
    return d;
}
__device__ __forceinline__ float hsum2(ull v) {
    float lo, hi;
    asm("mov.b64 {%0, %1}, %2;" : "=f"(lo), "=f"(hi) : "l"(v));
    return lo + hi;
}

__global__ __launch_bounds__(BLOCK) void lstm_kernel(
    const float* __restrict__ x,     // [B, T, I]
    const float* __restrict__ Wih,   // [16, 8]
    const float* __restrict__ Whh,   // [16, 4]
    const float* __restrict__ bih,   // [16]
    const float* __restrict__ bhh,   // [16]
    const float* __restrict__ fcw,   // [1, 4]
    const float* __restrict__ fcb,   // [1]
    float* __restrict__ out,         // [B, 1]
    int B)
{
    // [buf][warp][half][ el*9 + step ]  (stride 9 -> conflict-free LDS/STS)
    __shared__ float4 sm[2][2][2][8 * 9];

    const int t    = threadIdx.x;
    const int w    = t >> 5;          // warp 0..1 — owns elements w*8..w*8+7
    const int lane = t & 31;
    const int el   = lane >> 2;       // element within warp, 0..7
    const int k    = lane & 3;        // hidden unit owned by this lane
    const int b    = blockIdx.x * EPB + w * 8 + el;

    // ---- Packed weights: gate r in {0:i,1:f,2:g,3:o}, row = 4r + k.
    // sigmoid(z)=0.5*tanh(0.5z)+0.5 -> fold 0.5 prescale into i/f/o rows.
    ull wx[4][4], wh[4][2], bia[4];
#pragma unroll
    for (int r = 0; r < 4; r++) {
        const int row = 4 * r + k;
        const float s = (r == 2) ? 1.0f : 0.5f;
#pragma unroll
        for (int j = 0; j < 4; j++)
            wx[r][j] = pack2(s * Wih[row * I_DIM + 2 * j], s * Wih[row * I_DIM + 2 * j + 1]);
        // recurrent weights permuted so slot m multiplies h_{k^m} (bfly mask m)
        wh[r][0] = pack2(s * Whh[row * 4 + (k ^ 0)], s * Whh[row * 4 + (k ^ 1)]);
        wh[r][1] = pack2(s * Whh[row * 4 + (k ^ 2)], s * Whh[row * 4 + (k ^ 3)]);
        bia[r] = pack2(s * (bih[row] + bhh[row]), 0.0f);
    }

    float hs = 0.f, hx1 = 0.f, hx2 = 0.f, hx3 = 0.f;   // h_k, h_{k^1}, h_{k^2}, h_{k^3}
    float c = 0.f;
    const unsigned FULL = 0xffffffffu;

    // ---- Staging map: 256 float4 per chunk (16 elem x 16 quads); 64 thr x 4 each.
    // f = t + 64*j: elem e = f>>4, quad q = f&15 -> [e>>3][q&1][(e&7)*9 + (q>>1)]
    const float4* xf4 = reinterpret_cast<const float4*>(x);
    int se[4], sh[4], ss[4];
    size_t gb[4];
#pragma unroll
    for (int j = 0; j < 4; j++) {
        const int f = t + 64 * j;
        const int e = f >> 4, q = f & 15;
        se[j] = e >> 3;                       // warp region
        sh[j] = q & 1;                        // half
        ss[j] = (e & 7) * 9 + (q >> 1);       // slot
        gb[j] = (size_t)(blockIdx.x * EPB + e) * (T_STEPS * 2) + q;
    }

    // Prologue: stage chunk 0.
#pragma unroll
    for (int j = 0; j < 4; j++) sm[0][se[j]][sh[j]][ss[j]] = xf4[gb[j]];
    __syncthreads();

    const float4* lo0 = &sm[0][w][0][el * 9];
    const float4* hi0 = &sm[0][w][1][el * 9];
    const float4* lo1 = &sm[1][w][0][el * 9];
    const float4* hi1 = &sm[1][w][1][el * 9];

    for (int ck = 0; ck < NCHUNK; ck++) {
        float4 pf[4];
        const bool more = (ck + 1 < NCHUNK);
        if (more) {
#pragma unroll
            for (int j = 0; j < 4; j++) pf[j] = xf4[gb[j] + (size_t)(ck + 1) * 16];
        }

        const float4* plo = (ck & 1) ? lo1 : lo0;
        const float4* phi = (ck & 1) ? hi1 : hi0;

#pragma unroll
        for (int sI = 0; sI < CH_STEPS; sI++) {
            const ulonglong2 xlo = *reinterpret_cast<const ulonglong2*>(plo + sI);
            const ulonglong2 xhi = *reinterpret_cast<const ulonglong2*>(phi + sI);

            const ull h01 = pack2(hs,  hx1);
            const ull h23 = pack2(hx2, hx3);

            // Four gate accumulators (x part pipelines off the critical path)
            float z[4];
#pragma unroll
            for (int r = 0; r < 4; r++) {
                ull acc = ffma2(wx[r][0], xlo.x, bia[r]);
                acc = ffma2(wx[r][1], xlo.y, acc);
                acc = ffma2(wx[r][2], xhi.x, acc);
                acc = ffma2(wx[r][3], xhi.y, acc);
                acc = ffma2(wh[r][0], h01, acc);     // recurrent (critical path)
                acc = ffma2(wh[r][1], h23, acc);
                z[r] = hsum2(acc);
            }

            // All four activations local — no gather round.
            const float ai = fmaf(tanh_fast(z[0]), 0.5f, 0.5f);
            const float af = fmaf(tanh_fast(z[1]), 0.5f, 0.5f);
            const float ag = tanh_fast(z[2]);
            const float ao = fmaf(tanh_fast(z[3]), 0.5f, 0.5f);

            c  = fmaf(af, c, ai * ag);
            hs = ao * tanh_fast(c);

            // ONE shuffle round: 3 parallel butterflies within the quad.
            hx1 = __shfl_xor_sync(FULL, hs, 1);
            hx2 = __shfl_xor_sync(FULL, hs, 2);
            hx3 = __shfl_xor_sync(FULL, hs, 3);
        }

        if (more) {
#pragma unroll
            for (int j = 0; j < 4; j++) sm[(ck + 1) & 1][se[j]][sh[j]][ss[j]] = pf[j];
        }
        __syncthreads();
    }

    // ---- final FC: quad reduction of h_k * fcw[k] ----
    float v = hs * fcw[k];
    v += __shfl_xor_sync(FULL, v, 1);
    v += __shfl_xor_sync(FULL, v, 2);
    if (k == 0) out[b] = v + fcb[0];
}

extern "C" void kernel_launch(void* const* d_in, const int* in_sizes, int n_in,
                              void* d_out, int out_size)
{
    const float* x    = (const float*)d_in[0];
    const float* Wih  = (const float*)d_in[1];
    const float* Whh  = (const float*)d_in[2];
    const float* bih  = (const float*)d_in[3];
    const float* bhh  = (const float*)d_in[4];
    const float* fcw  = (const float*)d_in[5];
    const float* fcb  = (const float*)d_in[6];
    float* out = (float*)d_out;

    const int B = in_sizes[0] / (T_STEPS * I_DIM);   // 4096
    const int grid = B / EPB;                        // 256 blocks of 2 warps

    lstm_kernel<<<grid, BLOCK>>>(x, Wih, Whh, bih, bhh, fcw, fcb, out, B);
}